// round 2
// baseline (speedup 1.0000x reference)
#include <cuda_runtime.h>

#define BDIM 512

#define QR_PLANE   (64*66)            // 4224 floats, stride 66 (264B rows, 8B aligned)
#define QR_FLOATS  (10*QR_PLANE)      // 42240
#define VSTRIDE    68                 // 272B rows, left pad 2 -> aligned interior
#define VROWS      66
#define VSZ        (VROWS*VSTRIDE)    // 4488
#define WQ2_FLOATS 180                // 90 packed-dup f32x2 weights
#define WK_FLOATS  172
#define XS_FLOATS  (2*68*68)          // 9248 (overlaps qr region, phases 0-1 only)
#define SMEM_FLOATS (QR_FLOATS + 2*VSZ + WQ2_FLOATS + WK_FLOATS)
#define SMEM_BYTES (SMEM_FLOATS*4)

typedef unsigned long long ull;

__device__ float g_Kq[162];   // [q=3x3][c=2][s=3][u=3] composed 2-stage conv weights
__device__ float g_bq[9];     // per-offset bias (h_b folded through r_w)

__constant__ float c_qw[10][2][3][3];
__constant__ float c_qb[10];
__constant__ float c_fc[8][10];

// ---------------- setup: collapse 150-ch hidden conv into 9 composed 3x3 kernels ---
__global__ void vin_setup(const float* __restrict__ h_w,
                          const float* __restrict__ h_b,
                          const float* __restrict__ r_w)
{
    int t = threadIdx.x;
    if (t < 162) {
        int q = t / 18;
        int rest = t % 18;            // c*9 + s*3 + u
        float acc = 0.f;
        #pragma unroll 10
        for (int m = 0; m < 150; m++)
            acc += r_w[m*9 + q] * h_w[m*18 + rest];
        g_Kq[t] = acc;
    } else if (t < 171) {
        int q = t - 162;
        float acc = 0.f;
        #pragma unroll 10
        for (int m = 0; m < 150; m++)
            acc += r_w[m*9 + q] * h_b[m];
        g_bq[q] = acc;
    }
}

// ---------------- packed f32x2 helpers -------------------------------------------
__device__ __forceinline__ ull pk2(float lo, float hi){
    ull r;
    asm("mov.b64 %0, {%1, %2};" : "=l"(r) : "f"(lo), "f"(hi));
    return r;
}
__device__ __forceinline__ void upk2(ull v, float& lo, float& hi){
    asm("mov.b64 {%0, %1}, %2;" : "=f"(lo), "=f"(hi) : "l"(v));
}
__device__ __forceinline__ ull fma2(ull a, ull b, ull c){
    ull d;
    asm("fma.rn.f32x2 %0, %1, %2, %3;" : "=l"(d) : "l"(a), "l"(b), "l"(c));
    return d;
}

// ---------------- main: one CTA per image, whole VI loop in SMEM ------------------
__global__ void __launch_bounds__(BDIM, 1)
vin_main(const float* __restrict__ xg,
         const int*   __restrict__ pos_x,
         const int*   __restrict__ pos_y,
         const float* __restrict__ r_b,
         const float* __restrict__ q_w,
         float*       __restrict__ out)
{
    extern __shared__ float smem[];
    float* qrS  = smem;                       // 42240 floats, [a][row][col] stride 66
    float* vA   = smem + QR_FLOATS;           // 66x68, pad: rows 0&65, cols 0,1,66,67
    float* wq2f = vA + 2*VSZ;                 // 90 packed-dup loop weights (f32x2)
    float* wK   = wq2f + WQ2_FLOATS;          // composed r-conv weights (171)
    float* xsS  = smem;                       // x tile 2x68x68 (pad 2), overlaps qrS
    ull*   wq2  = (ull*)wq2f;

    const int b   = blockIdx.x;
    const int tid = threadIdx.x;
    const int row = tid >> 3;                 // 0..63
    const int cg  = tid & 7;
    const int c0  = cg << 3;                  // 8 pixels per thread, one row strip

    // ---- phase 0: zero pads, stage weights, load x --------------------------------
    for (int i = tid; i < XS_FLOATS; i += BDIM) xsS[i] = 0.f;
    for (int i = tid; i < 2*VSZ; i += BDIM) vA[i] = 0.f;
    if (tid < 171) wK[tid] = (tid < 162) ? g_Kq[tid] : g_bq[tid - 162];
    if (tid >= 256 && tid < 256 + 90) {       // pack loop weights (v-channel of q_w)
        int i = tid - 256;                    // i = a*9 + s*3 + u
        int a = i / 9, t9 = i % 9;
        float w = q_w[a*18 + 9 + t9];
        wq2f[2*i] = w; wq2f[2*i+1] = w;
    }
    __syncthreads();

    const float* xb = xg + (size_t)b * 8192;
    for (int i = tid; i < 8192; i += BDIM) {
        int c = i >> 12;
        int y = (i >> 6) & 63;
        int x = i & 63;
        xsS[c*4624 + (y+2)*68 + (x+2)] = xb[i];
    }
    __syncthreads();

    // ---- phase 1: r = composed(h_w,r_w) conv of x, exact boundary masking ---------
    {
        float racc[8];
        const float rb = r_b[0];
        #pragma unroll
        for (int p = 0; p < 8; p++) racc[p] = rb;
        #pragma unroll
        for (int q = 0; q < 9; q++) {
            const int qi = q / 3, qj = q % 3;
            const int yy = row + qi - 1;
            const bool rowok = (yy >= 0) && (yy < 64);
            float kw[18];
            #pragma unroll
            for (int t = 0; t < 18; t++) kw[t] = wK[q*18 + t];
            const float bqv = wK[162 + q];
            #pragma unroll
            for (int p = 0; p < 8; p++) {
                int xx = c0 + p + qj - 1;
                if (rowok && xx >= 0 && xx < 64) {
                    float t = bqv;
                    #pragma unroll
                    for (int c = 0; c < 2; c++)
                        #pragma unroll
                        for (int s = 0; s < 3; s++)
                            #pragma unroll
                            for (int u = 0; u < 3; u++)
                                t += kw[c*9 + s*3 + u] *
                                     xsS[c*4624 + (yy+s+1)*68 + (xx+u+1)];
                    racc[p] += t;
                }
            }
        }
        #pragma unroll
        for (int p = 0; p < 8; p++) vA[(row+1)*VSTRIDE + c0 + p + 2] = racc[p];
    }
    __syncthreads();

    // ---- phase 2: loop-invariant qr = conv(r, q_w[:,0]) + q_b  (overwrites xs) ----
    {
        #pragma unroll
        for (int p = 0; p < 8; p++) {
            const int x = c0 + p;
            float win[9];
            #pragma unroll
            for (int s = 0; s < 3; s++)
                #pragma unroll
                for (int u = 0; u < 3; u++)
                    win[s*3+u] = vA[(row+s)*VSTRIDE + x + 1 + u];
            #pragma unroll
            for (int a = 0; a < 10; a++) {
                float t = c_qb[a];
                #pragma unroll
                for (int s = 0; s < 3; s++)
                    #pragma unroll
                    for (int u = 0; u < 3; u++)
                        t += c_qw[a][0][s][u] * win[s*3+u];
                qrS[a*QR_PLANE + row*66 + x] = t;
            }
        }
    }
    __syncthreads();
    // clear vA (held r): v0 = 0
    for (int i = tid; i < VSZ; i += BDIM) vA[i] = 0.f;
    __syncthreads();

    // ---- phase 3: K=50 value-iteration steps, all in SMEM, packed f32x2 -----------
    const int qbase = row*66 + c0;            // 8B-aligned (264B rows, c0 even)
    const int wb    = row*VSTRIDE + c0 + 1;   // window base in v (smem row = in row-1)
    const int ob    = (row+1)*VSTRIDE + c0 + 2;
    int sw = 0;

    #pragma unroll 1
    for (int k = 0; k < 50; k++) {
        const float* vin  = vA + sw;
        float*       vout = vA + (sw ^ VSZ);
        sw ^= VSZ;

        float w0[10], w1[10], w2[10];
        #pragma unroll
        for (int i = 0; i < 10; i++) {
            w0[i] = vin[wb + i];
            w1[i] = vin[wb + VSTRIDE + i];
            w2[i] = vin[wb + 2*VSTRIDE + i];
        }
        ull pk[3][9];
        #pragma unroll
        for (int j = 0; j < 9; j++) {
            pk[0][j] = pk2(w0[j], w0[j+1]);
            pk[1][j] = pk2(w1[j], w1[j+1]);
            pk[2][j] = pk2(w2[j], w2[j+1]);
        }

        float vnew[8];
        #pragma unroll
        for (int a = 0; a < 10; a++) {
            ull acc[4];
            const ull* qp = (const ull*)(qrS + a*QR_PLANE + qbase);
            #pragma unroll
            for (int p = 0; p < 4; p++) acc[p] = qp[p];
            #pragma unroll
            for (int s = 0; s < 3; s++)
                #pragma unroll
                for (int u = 0; u < 3; u++) {
                    const ull wd = wq2[a*9 + s*3 + u];   // broadcast LDS.64
                    #pragma unroll
                    for (int p = 0; p < 4; p++)
                        acc[p] = fma2(pk[s][2*p + u], wd, acc[p]);
                }
            #pragma unroll
            for (int p = 0; p < 4; p++) {
                float lo, hi; upk2(acc[p], lo, hi);
                if (a == 0) { vnew[2*p] = lo; vnew[2*p+1] = hi; }
                else {
                    vnew[2*p]   = fmaxf(vnew[2*p], lo);
                    vnew[2*p+1] = fmaxf(vnew[2*p+1], hi);
                }
            }
        }
        #pragma unroll
        for (int px = 0; px < 8; px++) vout[ob + px] = vnew[px];
        __syncthreads();
    }
    // after 50 iters the final v lives in vA (k=49 wrote vA)

    const int prow = pos_x[b];
    const int pcol = pos_y[b];
    if (row == prow && (pcol >> 3) == cg) {
        float win[9];
        #pragma unroll
        for (int s = 0; s < 3; s++)
            #pragma unroll
            for (int u = 0; u < 3; u++)
                win[s*3+u] = vA[(prow+s)*VSTRIDE + pcol + 1 + u];
        float qv[10];
        #pragma unroll
        for (int a = 0; a < 10; a++) {
            float t = qrS[a*QR_PLANE + prow*66 + pcol];
            #pragma unroll
            for (int s = 0; s < 3; s++)
                #pragma unroll
                for (int u = 0; u < 3; u++)
                    t += c_qw[a][1][s][u] * win[s*3+u];
            qv[a] = t;
        }
        #pragma unroll
        for (int j = 0; j < 8; j++) {
            float o = 0.f;
            #pragma unroll
            for (int a = 0; a < 10; a++) o += qv[a] * c_fc[j][a];
            out[b*8 + j] = o;
        }
    }
}

// ---------------- launch ----------------------------------------------------------
extern "C" void kernel_launch(void* const* d_in, const int* in_sizes, int n_in,
                              void* d_out, int out_size)
{
    const float* x     = (const float*)d_in[0];
    const int*   pos_x = (const int*)  d_in[1];
    const int*   pos_y = (const int*)  d_in[2];
    const float* h_w   = (const float*)d_in[3];
    const float* h_b   = (const float*)d_in[4];
    const float* r_w   = (const float*)d_in[5];
    const float* r_b   = (const float*)d_in[6];
    const float* q_w   = (const float*)d_in[7];
    const float* q_b   = (const float*)d_in[8];
    const float* fc_w  = (const float*)d_in[9];

    (void)in_sizes; (void)n_in; (void)out_size;

    cudaFuncSetAttribute(vin_main, cudaFuncAttributeMaxDynamicSharedMemorySize,
                         SMEM_BYTES);

    cudaMemcpyToSymbolAsync(c_qw, q_w, 180*sizeof(float), 0,
                            cudaMemcpyDeviceToDevice, 0);
    cudaMemcpyToSymbolAsync(c_qb, q_b, 10*sizeof(float), 0,
                            cudaMemcpyDeviceToDevice, 0);
    cudaMemcpyToSymbolAsync(c_fc, fc_w, 80*sizeof(float), 0,
                            cudaMemcpyDeviceToDevice, 0);

    vin_setup<<<1, 192>>>(h_w, h_b, r_w);
    vin_main<<<128, BDIM, SMEM_BYTES>>>(x, pos_x, pos_y, r_b, q_w, (float*)d_out);
}

// round 4
// speedup vs baseline: 1.4676x; 1.4676x over previous
#include <cuda_runtime.h>
#include <math_constants.h>

#define BDIM 512

// qr2: per-thread contiguous, 41 ull stride (40 used + 1 pad -> conflict-free LDS.64)
#define QR2_STRIDE_ULL 41
#define QR2_FLOATS (BDIM * QR2_STRIDE_ULL * 2)   // 41984
#define VSTRIDE    66
#define VSZ        (66*66)                        // 4356
#define WQ2_FLOATS 90                             // 45 action-pair-packed f32x2
#define WK_FLOATS  172
#define XS_FLOATS  (2*68*68)                      // 9248, overlays qr2 (phases 0-1)
#define SMEM_FLOATS (QR2_FLOATS + 2*VSZ + WQ2_FLOATS + WK_FLOATS)
#define SMEM_BYTES (SMEM_FLOATS*4)

typedef unsigned long long ull;

__device__ float g_Kq[162];
__device__ float g_bq[9];

__constant__ float c_qw[10][2][3][3];
__constant__ float c_qb[10];
__constant__ float c_fc[8][10];

// ---------------- setup: collapse 150-ch hidden conv into 9 composed 3x3 kernels ---
__global__ void vin_setup(const float* __restrict__ h_w,
                          const float* __restrict__ h_b,
                          const float* __restrict__ r_w)
{
    int t = threadIdx.x;
    if (t < 162) {
        int q = t / 18;
        int rest = t % 18;
        float acc = 0.f;
        #pragma unroll 10
        for (int m = 0; m < 150; m++)
            acc += r_w[m*9 + q] * h_w[m*18 + rest];
        g_Kq[t] = acc;
    } else if (t < 171) {
        int q = t - 162;
        float acc = 0.f;
        #pragma unroll 10
        for (int m = 0; m < 150; m++)
            acc += r_w[m*9 + q] * h_b[m];
        g_bq[q] = acc;
    }
}

// ---------------- packed f32x2 helpers -------------------------------------------
__device__ __forceinline__ ull pk2(float lo, float hi){
    ull r;
    asm("mov.b64 %0, {%1, %2};" : "=l"(r) : "f"(lo), "f"(hi));
    return r;
}
__device__ __forceinline__ void upk2(ull v, float& lo, float& hi){
    asm("mov.b64 {%0, %1}, %2;" : "=f"(lo), "=f"(hi) : "l"(v));
}
__device__ __forceinline__ ull fma2(ull a, ull b, ull c){
    ull d;
    asm("fma.rn.f32x2 %0, %1, %2, %3;" : "=l"(d) : "l"(a), "l"(b), "l"(c));
    return d;
}

// ---------------- main: one CTA per image, whole VI loop in SMEM ------------------
__global__ void __launch_bounds__(BDIM, 1)
vin_main(const float* __restrict__ xg,
         const int*   __restrict__ pos_x,
         const int*   __restrict__ pos_y,
         const float* __restrict__ r_b,
         const float* __restrict__ q_w,
         float*       __restrict__ out)
{
    extern __shared__ float smem[];
    float* qr2f = smem;                       // per-thread qr, action-pair packed
    float* vA   = smem + QR2_FLOATS;          // 66x66, zero ring pad
    float* vB   = vA + VSZ;
    float* wq2f = vB + VSZ;                   // 45 action-pair weight pairs
    float* wK   = wq2f + WQ2_FLOATS;          // composed r-conv weights (171)
    float* xsS  = smem;                       // x tile 2x68x68, overlays qr2
    ull*   qr2  = (ull*)qr2f;
    ull*   wq2  = (ull*)wq2f;

    const int b   = blockIdx.x;
    const int tid = threadIdx.x;
    const int row = tid >> 3;                 // 0..63
    const int cg  = tid & 7;
    const int c0  = cg << 3;                  // 8 pixels per thread

    // ---- phase 0: zero pads, stage weights, load x --------------------------------
    for (int i = tid; i < XS_FLOATS; i += BDIM) xsS[i] = 0.f;
    for (int i = tid; i < 2*VSZ; i += BDIM) vA[i] = 0.f;
    if (tid < 171) wK[tid] = (tid < 162) ? g_Kq[tid] : g_bq[tid - 162];
    if (tid >= 256 && tid < 256 + 90) {
        // pack (w_a, w_{a+1}) action pairs of q_w's v-channel
        int i  = tid - 256;                   // i = a*9 + t9
        int a  = i / 9, t9 = i % 9;
        wq2f[(a >> 1)*18 + t9*2 + (a & 1)] = q_w[a*18 + 9 + t9];
    }
    __syncthreads();

    const float* xb = xg + (size_t)b * 8192;
    for (int i = tid; i < 8192; i += BDIM) {
        int c = i >> 12;
        int y = (i >> 6) & 63;
        int x = i & 63;
        xsS[c*4624 + (y+2)*68 + (x+2)] = xb[i];
    }
    __syncthreads();

    // ---- phase 1: r = composed conv of x, exact boundary masking ------------------
    {
        float racc[8];
        const float rb = r_b[0];
        #pragma unroll
        for (int p = 0; p < 8; p++) racc[p] = rb;
        #pragma unroll
        for (int q = 0; q < 9; q++) {
            const int qi = q / 3, qj = q % 3;
            const int yy = row + qi - 1;
            const bool rowok = (yy >= 0) && (yy < 64);
            float kw[18];
            #pragma unroll
            for (int t = 0; t < 18; t++) kw[t] = wK[q*18 + t];
            const float bqv = wK[162 + q];
            #pragma unroll
            for (int p = 0; p < 8; p++) {
                int xx = c0 + p + qj - 1;
                if (rowok && xx >= 0 && xx < 64) {
                    float t = bqv;
                    #pragma unroll
                    for (int c = 0; c < 2; c++)
                        #pragma unroll
                        for (int s = 0; s < 3; s++)
                            #pragma unroll
                            for (int u = 0; u < 3; u++)
                                t += kw[c*9 + s*3 + u] *
                                     xsS[c*4624 + (yy+s+1)*68 + (xx+u+1)];
                    racc[p] += t;
                }
            }
        }
        __syncthreads();   // all reads of xsS done before qr2 overlay is written? no—
        // (xsS overlays qr2, but phase 2 writes qr2 AFTER this barrier; racc in regs)
        #pragma unroll
        for (int p = 0; p < 8; p++) vA[(row+1)*VSTRIDE + c0 + p + 1] = racc[p];
    }
    __syncthreads();

    // ---- phase 2: loop-invariant qr = conv(r, q_w[:,0]) + q_b, action-pair layout --
    {
        ull* myqr = qr2 + (size_t)tid * QR2_STRIDE_ULL;
        #pragma unroll
        for (int p = 0; p < 8; p++) {
            const int x = c0 + p;
            float win[9];
            #pragma unroll
            for (int s = 0; s < 3; s++)
                #pragma unroll
                for (int u = 0; u < 3; u++)
                    win[s*3+u] = vA[(row+s)*VSTRIDE + x + u];
            float qt[10];
            #pragma unroll
            for (int a = 0; a < 10; a++) {
                float t = c_qb[a];
                #pragma unroll
                for (int s = 0; s < 3; s++)
                    #pragma unroll
                    for (int u = 0; u < 3; u++)
                        t += c_qw[a][0][s][u] * win[s*3+u];
                qt[a] = t;
            }
            #pragma unroll
            for (int ap = 0; ap < 5; ap++)
                myqr[p*5 + ap] = pk2(qt[2*ap], qt[2*ap+1]);
        }
    }
    __syncthreads();
    // clear vA (held r): v0 = 0
    for (int i = tid; i < VSZ; i += BDIM) vA[i] = 0.f;
    __syncthreads();

    // ---- phase 3: K=50 VI steps, action-pair packed f32x2 -------------------------
    const int wb = row*VSTRIDE + c0;          // window base (rows row..row+2, cols c0..c0+9)
    const int ob = (row+1)*VSTRIDE + c0 + 1;
    ull* const myqr = qr2 + (size_t)tid * QR2_STRIDE_ULL;
    int sw = 0;

    #pragma unroll 1
    for (int k = 0; k < 50; k++) {
        const float* vin  = vA + sw;
        float*       vout = vA + (sw ^ VSZ);
        sw ^= VSZ;

        // duplicated window: 3 rows x 10 cols, (v,v) pairs
        ull dw[30];
        #pragma unroll
        for (int s = 0; s < 3; s++)
            #pragma unroll
            for (int j = 0; j < 10; j++) {
                float v = vin[wb + s*VSTRIDE + j];
                dw[s*10 + j] = pk2(v, v);
            }

        float vnew[8];
        #pragma unroll
        for (int p = 0; p < 8; p++) vnew[p] = -CUDART_INF_F;

        #pragma unroll 1
        for (int ap = 0; ap < 5; ap++) {
            ull w[9];
            #pragma unroll
            for (int t = 0; t < 9; t++) w[t] = wq2[ap*9 + t];   // broadcast LDS.64
            const ull* qp = myqr + ap;
            #pragma unroll
            for (int p = 0; p < 8; p++) {
                ull acc = qp[p*5];
                #pragma unroll
                for (int s = 0; s < 3; s++)
                    #pragma unroll
                    for (int u = 0; u < 3; u++)
                        acc = fma2(dw[s*10 + p + u], w[s*3+u], acc);
                float lo, hi; upk2(acc, lo, hi);
                vnew[p] = fmaxf(vnew[p], fmaxf(lo, hi));
            }
        }
        #pragma unroll
        for (int p = 0; p < 8; p++) vout[ob + p] = vnew[p];
        __syncthreads();
    }
    // final v lives in vA (k=49 wrote vA)

    const int prow = pos_x[b];
    const int pcol = pos_y[b];
    if (row == prow && (pcol >> 3) == cg) {
        const int p = pcol & 7;
        float win[9];
        #pragma unroll
        for (int s = 0; s < 3; s++)
            #pragma unroll
            for (int u = 0; u < 3; u++)
                win[s*3+u] = vA[(prow+s)*VSTRIDE + pcol + u];
        float qv[10];
        #pragma unroll
        for (int ap = 0; ap < 5; ap++) {
            float lo, hi; upk2(myqr[p*5 + ap], lo, hi);
            qv[2*ap] = lo; qv[2*ap+1] = hi;
        }
        #pragma unroll
        for (int a = 0; a < 10; a++) {
            float t = qv[a];
            #pragma unroll
            for (int s = 0; s < 3; s++)
                #pragma unroll
                for (int u = 0; u < 3; u++)
                    t += c_qw[a][1][s][u] * win[s*3+u];
            qv[a] = t;
        }
        #pragma unroll
        for (int j = 0; j < 8; j++) {
            float o = 0.f;
            #pragma unroll
            for (int a = 0; a < 10; a++) o += qv[a] * c_fc[j][a];
            out[b*8 + j] = o;
        }
    }
}

// ---------------- launch ----------------------------------------------------------
extern "C" void kernel_launch(void* const* d_in, const int* in_sizes, int n_in,
                              void* d_out, int out_size)
{
    const float* x     = (const float*)d_in[0];
    const int*   pos_x = (const int*)  d_in[1];
    const int*   pos_y = (const int*)  d_in[2];
    const float* h_w   = (const float*)d_in[3];
    const float* h_b   = (const float*)d_in[4];
    const float* r_w   = (const float*)d_in[5];
    const float* r_b   = (const float*)d_in[6];
    const float* q_w   = (const float*)d_in[7];
    const float* q_b   = (const float*)d_in[8];
    const float* fc_w  = (const float*)d_in[9];

    (void)in_sizes; (void)n_in; (void)out_size;

    cudaFuncSetAttribute(vin_main, cudaFuncAttributeMaxDynamicSharedMemorySize,
                         SMEM_BYTES);

    cudaMemcpyToSymbolAsync(c_qw, q_w, 180*sizeof(float), 0,
                            cudaMemcpyDeviceToDevice, 0);
    cudaMemcpyToSymbolAsync(c_qb, q_b, 10*sizeof(float), 0,
                            cudaMemcpyDeviceToDevice, 0);
    cudaMemcpyToSymbolAsync(c_fc, fc_w, 80*sizeof(float), 0,
                            cudaMemcpyDeviceToDevice, 0);

    vin_setup<<<1, 192>>>(h_w, h_b, r_w);
    vin_main<<<128, BDIM, SMEM_BYTES>>>(x, pos_x, pos_y, r_b, q_w, (float*)d_out);
}